// round 15
// baseline (speedup 1.0000x reference)
#include <cuda_runtime.h>
#include <cuda_bf16.h>
#include <math.h>
#include <stdint.h>

// ---------------- problem-size maxima ----------------
#define MAXN   50000
#define MAXE   400000
#define MAXET  (MAXE + MAXN)
#define MAXHC  512
#define MAXM   256

// ---------------- device scratch ----------------
__device__ int   g_src [MAXET];
__device__ int   g_dst [MAXET];
__device__ int   g_srcs[MAXET];
__device__ int   g_cnt [MAXN];
__device__ int   g_rp  [MAXN + 1];
__device__ int   g_cur [MAXN];
__device__ int   g_bsum[64];

__device__ float g_h1 [(size_t)MAXN * MAXHC];
__device__ float g_h2 [(size_t)MAXN * MAXM];
__device__ float g_hd [(size_t)MAXN * MAXM];
__device__ __nv_bfloat16 g_ahi[(size_t)MAXN * MAXHC];
__device__ __nv_bfloat16 g_alo[(size_t)MAXN * MAXHC];
__device__ __nv_bfloat16 g_wthi[512 * 512];
__device__ __nv_bfloat16 g_wtlo[512 * 512];
__device__ float g_as1[(size_t)MAXN * 4], g_ad1[(size_t)MAXN * 4];
__device__ float g_as2[MAXN], g_ad2[MAXN];
__device__ float g_asd[MAXN], g_add[MAXN];

// ---------------- PTX helpers ----------------
__device__ __forceinline__ uint32_t smem_u32(const void* p) {
    uint32_t a;
    asm("{ .reg .u64 t; cvta.to.shared.u64 t, %1; cvt.u32.u64 %0, t; }" : "=r"(a) : "l"(p));
    return a;
}
__device__ __forceinline__ void ldmx4(uint32_t* r, uint32_t addr) {
    asm volatile("ldmatrix.sync.aligned.m8n8.x4.shared.b16 {%0,%1,%2,%3}, [%4];"
        : "=r"(r[0]), "=r"(r[1]), "=r"(r[2]), "=r"(r[3]) : "r"(addr));
}
__device__ __forceinline__ void mma16816(float* c, const uint32_t* a,
                                         uint32_t b0, uint32_t b1) {
    asm volatile(
        "mma.sync.aligned.m16n8k16.row.col.f32.bf16.bf16.f32 "
        "{%0,%1,%2,%3}, {%4,%5,%6,%7}, {%8,%9}, {%0,%1,%2,%3};"
        : "+f"(c[0]), "+f"(c[1]), "+f"(c[2]), "+f"(c[3])
        : "r"(a[0]), "r"(a[1]), "r"(a[2]), "r"(a[3]), "r"(b0), "r"(b1));
}
// 8 fp32 (in two uint4) -> hi/lo bf16 split packed as two uint4 (8 bf16 each)
__device__ __forceinline__ void cvt8(uint4 r0, uint4 r1, uint4& h, uint4& l) {
    float v[8];
    *(uint4*)&v[0] = r0; *(uint4*)&v[4] = r1;
    __nv_bfloat162 hh[4], ll[4];
#pragma unroll
    for (int i = 0; i < 4; i++) {
        __nv_bfloat16 a = __float2bfloat16(v[2 * i]);
        __nv_bfloat16 b = __float2bfloat16(v[2 * i + 1]);
        hh[i].x = a; hh[i].y = b;
        ll[i].x = __float2bfloat16(v[2 * i]     - __bfloat162float(a));
        ll[i].y = __float2bfloat16(v[2 * i + 1] - __bfloat162float(b));
    }
    h = *(uint4*)hh; l = *(uint4*)ll;
}

// ---------------- graph-building kernels ----------------
__global__ void build_edges(const void* __restrict__ ei, int E, int Nn) {
    __shared__ int s_is64;
    if (threadIdx.x == 0) {
        const int* p = (const int*)ei;
        int nz = 0;
        int cnt = E < 64 ? E : 64;
        for (int i = 0; i < cnt; i++) nz |= p[2 * i + 1];
        s_is64 = (nz == 0) ? 1 : 0;
    }
    __syncthreads();
    int i = blockIdx.x * blockDim.x + threadIdx.x;
    int tot = E + Nn;
    if (i >= tot) return;
    int s, d;
    if (i < E) {
        if (s_is64) {
            const long long* p = (const long long*)ei;
            s = (int)p[i]; d = (int)p[E + i];
        } else {
            const int* p = (const int*)ei;
            s = p[i]; d = p[E + i];
        }
    } else { s = d = i - E; }
    g_src[i] = s; g_dst[i] = d;
}
__global__ void zero_int(int* p, int n) {
    int i = blockIdx.x * blockDim.x + threadIdx.x;
    if (i < n) p[i] = 0;
}
__global__ void zero_f2(float* a, float* b, int n) {
    int i = blockIdx.x * blockDim.x + threadIdx.x;
    if (i < n) { a[i] = 0.f; b[i] = 0.f; }
}
__global__ void hist_kernel(int tot) {
    int i = blockIdx.x * blockDim.x + threadIdx.x;
    if (i < tot) atomicAdd(&g_cnt[g_dst[i]], 1);
}
// two-level scan
__global__ void scan1_kernel(int n) {
    __shared__ int sh[1024];
    int tx = threadIdx.x;
    int i = blockIdx.x * 1024 + tx;
    int v = (i < n) ? g_cnt[i] : 0;
    sh[tx] = v;
    __syncthreads();
    for (int off = 1; off < 1024; off <<= 1) {
        int t = (tx >= off) ? sh[tx - off] : 0;
        __syncthreads();
        sh[tx] += t;
        __syncthreads();
    }
    if (i < n) g_rp[i + 1] = sh[tx];
    if (tx == 1023) g_bsum[blockIdx.x] = sh[1023];
}
__global__ void scan2_kernel(int nb) {
    __shared__ int sh[64];
    int tx = threadIdx.x;
    int v = (tx < nb) ? g_bsum[tx] : 0;
    sh[tx] = v;
    __syncthreads();
    for (int off = 1; off < 64; off <<= 1) {
        int t = (tx >= off) ? sh[tx - off] : 0;
        __syncthreads();
        sh[tx] += t;
        __syncthreads();
    }
    if (tx < nb) g_bsum[tx] = sh[tx];
}
__global__ void scan3_kernel(int n) {
    int i = blockIdx.x * blockDim.x + threadIdx.x;
    if (i == 0) g_rp[0] = 0;
    if (i < n) {
        int b = i >> 10;
        if (b > 0) g_rp[i + 1] += g_bsum[b - 1];
    }
}
__global__ void copy_cursor(int n) {
    int i = blockIdx.x * blockDim.x + threadIdx.x;
    if (i < n) g_cur[i] = g_rp[i];
}
__global__ void scatter_kernel(int tot) {
    int i = blockIdx.x * blockDim.x + threadIdx.x;
    if (i >= tot) return;
    int d = g_dst[i];
    int pos = atomicAdd(&g_cur[d], 1);
    g_srcs[pos] = g_src[i];
}

// ---------------- bf16 split of W^T ----------------
__global__ void wtsplit_kernel(const float* __restrict__ W,
                               __nv_bfloat16* __restrict__ hi,
                               __nv_bfloat16* __restrict__ lo, int K, int N) {
    int idx = blockIdx.x * blockDim.x + threadIdx.x;
    if (idx >= K * N) return;
    int k = idx / N, n = idx - k * N;
    float v = W[idx];
    __nv_bfloat16 h = __float2bfloat16(v);
    hi[(size_t)n * K + k] = h;
    lo[(size_t)n * K + k] = __float2bfloat16(v - __bfloat162float(h));
}

// ---------------- split-bf16 tensor-core GEMM + fused alpha epilogue ---------
// C[M,N] = A[M,K] @ (Bt hi/lo[N,K])^T, fp32 accumulate.
// A is either presplit bf16 (Ahi/Alo) or raw fp32 (a_fp32=1, split in-kernel).
// CTA tile 128x64, BK=32, 8 warps (4M x 2N), warp tile 32x32.
// MMA issue order: all 8 accumulators per split-term (HH, HL, LH) so each
// accumulator's dependent HMMAs are 8 instructions apart (latency covered).
__global__ void __launch_bounds__(256, 2)
mma_gemm(const __nv_bfloat16* __restrict__ Ahi, const __nv_bfloat16* __restrict__ Alo,
         const __nv_bfloat16* __restrict__ Bhi, const __nv_bfloat16* __restrict__ Blo,
         float* __restrict__ C, int M, int K, int N,
         const float* __restrict__ asrc, const float* __restrict__ adst,
         float* __restrict__ as_, float* __restrict__ ad_, int H, int Ch,
         int a_fp32) {
    __shared__ __align__(16) uint8_t sAh[128 * 80], sAl[128 * 80];
    __shared__ __align__(16) uint8_t sBh[64 * 80],  sBl[64 * 80];
    int tid = threadIdx.x, lane = tid & 31, wid = tid >> 5;
    int wm = wid & 3, wn = wid >> 2;
    int m0 = blockIdx.y * 128, n0 = blockIdx.x * 64;

    int lr = tid >> 2, lc = tid & 3;
    int gm0 = m0 + lr, gm1 = m0 + lr + 64;
    const size_t a0off = (size_t)gm0 * K + lc * 8;
    const size_t a1off = (size_t)gm1 * K + lc * 8;
    const size_t bOff  = (size_t)(n0 + lr) * K + lc * 8;
    uint32_t stA0 = (uint32_t)(lr * 80 + lc * 16);
    uint32_t stA1 = (uint32_t)((lr + 64) * 80 + lc * 16);
    const float* X = (const float*)Ahi;   // when a_fp32

    uint32_t sAhB = smem_u32(sAh), sAlB = smem_u32(sAl);
    uint32_t sBhB = smem_u32(sBh), sBlB = smem_u32(sBl);

    uint32_t aoffs[2], boffs[2];
#pragma unroll
    for (int mt = 0; mt < 2; mt++)
        aoffs[mt] = (uint32_t)((wm * 32 + mt * 16 + (lane & 15)) * 80 + (lane >> 4) * 16);
#pragma unroll
    for (int p = 0; p < 2; p++)
        boffs[p] = (uint32_t)((wn * 32 + p * 16 + ((lane >> 3) & 1) * 8 + (lane & 7)) * 80
                              + (lane >> 4) * 16);

    float acc[2][4][4];
#pragma unroll
    for (int i = 0; i < 2; i++)
#pragma unroll
        for (int j = 0; j < 4; j++)
#pragma unroll
            for (int q = 0; q < 4; q++) acc[i][j][q] = 0.f;

    const uint4 z4 = make_uint4(0, 0, 0, 0);
    uint4 pa0h, pa1h, pa0l, pa1l, pbh, pbl;
    if (a_fp32) {
        const uint4* p0 = (const uint4*)(X + a0off);
        const uint4* p1 = (const uint4*)(X + a1off);
        pa0h = (gm0 < M) ? p0[0] : z4;  pa0l = (gm0 < M) ? p0[1] : z4;
        pa1h = (gm1 < M) ? p1[0] : z4;  pa1l = (gm1 < M) ? p1[1] : z4;
    } else {
        pa0h = (gm0 < M) ? *(const uint4*)(Ahi + a0off) : z4;
        pa1h = (gm1 < M) ? *(const uint4*)(Ahi + a1off) : z4;
        pa0l = (gm0 < M) ? *(const uint4*)(Alo + a0off) : z4;
        pa1l = (gm1 < M) ? *(const uint4*)(Alo + a1off) : z4;
    }
    pbh = *(const uint4*)(Bhi + bOff);
    pbl = *(const uint4*)(Blo + bOff);

    int nch = K >> 5;
    for (int ch = 0; ch < nch; ch++) {
        if (a_fp32) {
            uint4 h0, l0, h1, l1;
            cvt8(pa0h, pa0l, h0, l0);
            cvt8(pa1h, pa1l, h1, l1);
            *(uint4*)(sAh + stA0) = h0;
            *(uint4*)(sAl + stA0) = l0;
            *(uint4*)(sAh + stA1) = h1;
            *(uint4*)(sAl + stA1) = l1;
        } else {
            *(uint4*)(sAh + stA0) = pa0h;
            *(uint4*)(sAh + stA1) = pa1h;
            *(uint4*)(sAl + stA0) = pa0l;
            *(uint4*)(sAl + stA1) = pa1l;
        }
        *(uint4*)(sBh + stA0) = pbh;
        *(uint4*)(sBl + stA0) = pbl;
        __syncthreads();

        if (ch + 1 < nch) {
            int k8 = (ch + 1) * 32;
            if (a_fp32) {
                const uint4* p0 = (const uint4*)(X + a0off + k8);
                const uint4* p1 = (const uint4*)(X + a1off + k8);
                pa0h = (gm0 < M) ? p0[0] : z4;  pa0l = (gm0 < M) ? p0[1] : z4;
                pa1h = (gm1 < M) ? p1[0] : z4;  pa1l = (gm1 < M) ? p1[1] : z4;
            } else {
                pa0h = (gm0 < M) ? *(const uint4*)(Ahi + a0off + k8) : z4;
                pa1h = (gm1 < M) ? *(const uint4*)(Ahi + a1off + k8) : z4;
                pa0l = (gm0 < M) ? *(const uint4*)(Alo + a0off + k8) : z4;
                pa1l = (gm1 < M) ? *(const uint4*)(Alo + a1off + k8) : z4;
            }
            pbh = *(const uint4*)(Bhi + bOff + k8);
            pbl = *(const uint4*)(Blo + bOff + k8);
        }

#pragma unroll
        for (int ks = 0; ks < 2; ks++) {
            uint32_t AH[2][4], AL[2][4], BH[2][4], BL[2][4];
            ldmx4(AH[0], sAhB + aoffs[0] + ks * 32);
            ldmx4(AH[1], sAhB + aoffs[1] + ks * 32);
            ldmx4(AL[0], sAlB + aoffs[0] + ks * 32);
            ldmx4(AL[1], sAlB + aoffs[1] + ks * 32);
            ldmx4(BH[0], sBhB + boffs[0] + ks * 32);
            ldmx4(BH[1], sBhB + boffs[1] + ks * 32);
            ldmx4(BL[0], sBlB + boffs[0] + ks * 32);
            ldmx4(BL[1], sBlB + boffs[1] + ks * 32);
            // term 1: AH x BH -- 8 independent accumulators back-to-back
#pragma unroll
            for (int mt = 0; mt < 2; mt++)
#pragma unroll
                for (int p = 0; p < 2; p++) {
                    mma16816(acc[mt][p * 2 + 0], AH[mt], BH[p][0], BH[p][2]);
                    mma16816(acc[mt][p * 2 + 1], AH[mt], BH[p][1], BH[p][3]);
                }
            // term 2: AH x BL
#pragma unroll
            for (int mt = 0; mt < 2; mt++)
#pragma unroll
                for (int p = 0; p < 2; p++) {
                    mma16816(acc[mt][p * 2 + 0], AH[mt], BL[p][0], BL[p][2]);
                    mma16816(acc[mt][p * 2 + 1], AH[mt], BL[p][1], BL[p][3]);
                }
            // term 3: AL x BH
#pragma unroll
            for (int mt = 0; mt < 2; mt++)
#pragma unroll
                for (int p = 0; p < 2; p++) {
                    mma16816(acc[mt][p * 2 + 0], AL[mt], BH[p][0], BH[p][2]);
                    mma16816(acc[mt][p * 2 + 1], AL[mt], BH[p][1], BH[p][3]);
                }
        }
        __syncthreads();
    }

    // ---- epilogue: store C + fused alpha partials ----
    int hh = n0 / Ch;
#pragma unroll
    for (int mt = 0; mt < 2; mt++) {
        int gr0 = m0 + wm * 32 + mt * 16 + (lane >> 2);
        int gr1 = gr0 + 8;
        float ps0 = 0.f, pd0 = 0.f, ps1 = 0.f, pd1 = 0.f;
#pragma unroll
        for (int nt = 0; nt < 4; nt++) {
            int gc = n0 + wn * 32 + nt * 8 + (lane & 3) * 2;
            float a0 = asrc[gc], a1 = asrc[gc + 1];
            float d0 = adst[gc], d1 = adst[gc + 1];
            ps0 = fmaf(acc[mt][nt][0], a0, fmaf(acc[mt][nt][1], a1, ps0));
            pd0 = fmaf(acc[mt][nt][0], d0, fmaf(acc[mt][nt][1], d1, pd0));
            ps1 = fmaf(acc[mt][nt][2], a0, fmaf(acc[mt][nt][3], a1, ps1));
            pd1 = fmaf(acc[mt][nt][2], d0, fmaf(acc[mt][nt][3], d1, pd1));
            if (gr0 < M)
                *(float2*)(C + (size_t)gr0 * N + gc) = make_float2(acc[mt][nt][0], acc[mt][nt][1]);
            if (gr1 < M)
                *(float2*)(C + (size_t)gr1 * N + gc) = make_float2(acc[mt][nt][2], acc[mt][nt][3]);
        }
#pragma unroll
        for (int o = 1; o <= 2; o <<= 1) {
            ps0 += __shfl_xor_sync(0xffffffffu, ps0, o);
            pd0 += __shfl_xor_sync(0xffffffffu, pd0, o);
            ps1 += __shfl_xor_sync(0xffffffffu, ps1, o);
            pd1 += __shfl_xor_sync(0xffffffffu, pd1, o);
        }
        if ((lane & 3) == 0) {
            if (gr0 < M) {
                atomicAdd(&as_[(size_t)gr0 * H + hh], ps0);
                atomicAdd(&ad_[(size_t)gr0 * H + hh], pd0);
            }
            if (gr1 < M) {
                atomicAdd(&as_[(size_t)gr1 * H + hh], ps1);
                atomicAdd(&ad_[(size_t)gr1 * H + hh], pd1);
            }
        }
    }
}

// ---------------- GAT segment-softmax + aggregate (float4 channels) ----------
#define CHUNK 64
__global__ void gat_aggregate(const float* __restrict__ feat,
                              const float* __restrict__ as_,
                              const float* __restrict__ ad_,
                              const float* __restrict__ bias,
                              float* __restrict__ out,            // nullable
                              __nv_bfloat16* __restrict__ ohi,    // nullable
                              __nv_bfloat16* __restrict__ olo,
                              int H, int C, int prelu,
                              const float* __restrict__ prelu_a) {
    int n = blockIdx.x;
    int t = threadIdx.x;
    int HC = H * C;
    int t4 = t * 4;
    int h = t4 / C;
    __shared__ float sw[4 * CHUNK];
    __shared__ int   ssrc[CHUNK];
    int s0 = g_rp[n], s1 = g_rp[n + 1];
    int warp = t >> 5, lane = t & 31;

    float m = 0.f, rdn = 0.f, ad = 0.f;
    if (warp < H) {
        ad = ad_[(size_t)n * H + warp];
        m = -INFINITY;
        for (int k = s0 + lane; k < s1; k += 32) {
            float e = as_[(size_t)g_srcs[k] * H + warp] + ad;
            e = e > 0.f ? e : 0.2f * e;
            m = fmaxf(m, e);
        }
#pragma unroll
        for (int o = 16; o; o >>= 1) m = fmaxf(m, __shfl_xor_sync(0xffffffffu, m, o));
        float ds = 0.f;
        for (int k = s0 + lane; k < s1; k += 32) {
            float e = as_[(size_t)g_srcs[k] * H + warp] + ad;
            e = e > 0.f ? e : 0.2f * e;
            ds += __expf(e - m);
        }
#pragma unroll
        for (int o = 16; o; o >>= 1) ds += __shfl_xor_sync(0xffffffffu, ds, o);
        rdn = 1.f / (ds + 1e-16f);
    }

    float4 acc = make_float4(0.f, 0.f, 0.f, 0.f);
    for (int base = s0; base < s1; base += CHUNK) {
        int count = min(CHUNK, s1 - base);
        __syncthreads();
        if (warp < H) {
            for (int j = lane; j < count; j += 32) {
                int s = g_srcs[base + j];
                if (warp == 0) ssrc[j] = s;
                float e = as_[(size_t)s * H + warp] + ad;
                e = e > 0.f ? e : 0.2f * e;
                sw[warp * CHUNK + j] = __expf(e - m) * rdn;
            }
        }
        __syncthreads();
        const float* swh = sw + h * CHUNK;
        for (int j = 0; j < count; j++) {
            float4 f = *(const float4*)(feat + (size_t)ssrc[j] * HC + t4);
            float w = swh[j];
            acc.x = fmaf(f.x, w, acc.x);
            acc.y = fmaf(f.y, w, acc.y);
            acc.z = fmaf(f.z, w, acc.z);
            acc.w = fmaf(f.w, w, acc.w);
        }
    }

    float4 b4 = *(const float4*)(bias + t4);
    float v0 = acc.x + b4.x, v1 = acc.y + b4.y, v2 = acc.z + b4.z, v3 = acc.w + b4.w;
    if (prelu) {
        float a = prelu_a[0];
        v0 = v0 >= 0.f ? v0 : a * v0;
        v1 = v1 >= 0.f ? v1 : a * v1;
        v2 = v2 >= 0.f ? v2 : a * v2;
        v3 = v3 >= 0.f ? v3 : a * v3;
    }
    size_t idx = (size_t)n * HC + t4;
    if (out) {
        *(float4*)(out + idx) = make_float4(v0, v1, v2, v3);
    }
    if (ohi) {
        __nv_bfloat16 h0 = __float2bfloat16(v0);
        __nv_bfloat16 h1 = __float2bfloat16(v1);
        __nv_bfloat16 h2 = __float2bfloat16(v2);
        __nv_bfloat16 h3 = __float2bfloat16(v3);
        __nv_bfloat162 hh01; hh01.x = h0; hh01.y = h1;
        __nv_bfloat162 hh23; hh23.x = h2; hh23.y = h3;
        *(__nv_bfloat162*)(ohi + idx)     = hh01;
        *(__nv_bfloat162*)(ohi + idx + 2) = hh23;
        __nv_bfloat162 ll01;
        ll01.x = __float2bfloat16(v0 - __bfloat162float(h0));
        ll01.y = __float2bfloat16(v1 - __bfloat162float(h1));
        __nv_bfloat162 ll23;
        ll23.x = __float2bfloat16(v2 - __bfloat162float(h2));
        ll23.y = __float2bfloat16(v3 - __bfloat162float(h3));
        *(__nv_bfloat162*)(olo + idx)     = ll01;
        *(__nv_bfloat162*)(olo + idx + 2) = ll23;
    }
}

// ---------------- host orchestration ----------------
static inline int ceil_div(int a, int b) { return (a + b - 1) / b; }

static void run_gemm(const __nv_bfloat16* Ahi, const __nv_bfloat16* Alo,
                     const __nv_bfloat16* Bhi, const __nv_bfloat16* Blo,
                     float* C, int M, int K, int N,
                     const float* asrc, const float* adst,
                     float* as_, float* ad_, int H, int Ch, int a_fp32) {
    dim3 grid(N / 64, ceil_div(M, 128));
    mma_gemm<<<grid, 256>>>(Ahi, Alo, Bhi, Blo, C, M, K, N,
                            asrc, adst, as_, ad_, H, Ch, a_fp32);
}

extern "C" void kernel_launch(void* const* d_in, const int* in_sizes, int n_in,
                              void* d_out, int out_size) {
    const float* x       = (const float*)d_in[0];
    const void*  eidx    = d_in[1];
    const float* W1      = (const float*)d_in[2];
    const float* a_src1  = (const float*)d_in[3];
    const float* a_dst1  = (const float*)d_in[4];
    const float* b1      = (const float*)d_in[5];
    const float* prelu_a = (const float*)d_in[6];
    const float* W2      = (const float*)d_in[7];
    const float* a_src2  = (const float*)d_in[8];
    const float* a_dst2  = (const float*)d_in[9];
    const float* b2      = (const float*)d_in[10];
    const float* Wd      = (const float*)d_in[11];
    const float* a_srcd  = (const float*)d_in[12];
    const float* a_dstd  = (const float*)d_in[13];
    const float* bd      = (const float*)d_in[14];

    const int HHc = in_sizes[3];          // 512
    const int H1  = 4;
    const int C1  = HHc / H1;             // 128
    const int M   = in_sizes[8];          // 256
    const int D   = in_sizes[12];         // 256
    const int N   = in_sizes[0] / D;      // 50000
    const int E   = in_sizes[1] / 2;      // 400000
    const int ET  = E + N;

    float* out   = (float*)d_out;
    float* z     = out;
    float* x_hat = out + (size_t)N * M;

    float *h1, *h2, *hd;
    float *as1, *ad1, *as2, *ad2, *asd, *add;
    __nv_bfloat16 *ahi, *alo, *wthi, *wtlo;
    int *cnt_p;
    cudaGetSymbolAddress((void**)&h1,  g_h1);
    cudaGetSymbolAddress((void**)&h2,  g_h2);
    cudaGetSymbolAddress((void**)&hd,  g_hd);
    cudaGetSymbolAddress((void**)&ahi, g_ahi);
    cudaGetSymbolAddress((void**)&alo, g_alo);
    cudaGetSymbolAddress((void**)&wthi, g_wthi);
    cudaGetSymbolAddress((void**)&wtlo, g_wtlo);
    cudaGetSymbolAddress((void**)&as1, g_as1);
    cudaGetSymbolAddress((void**)&ad1, g_ad1);
    cudaGetSymbolAddress((void**)&as2, g_as2);
    cudaGetSymbolAddress((void**)&ad2, g_ad2);
    cudaGetSymbolAddress((void**)&asd, g_asd);
    cudaGetSymbolAddress((void**)&add, g_add);
    cudaGetSymbolAddress((void**)&cnt_p, g_cnt);

    // ---- layer 1 GEMM (x split fused in-kernel); gemm1 stays 4th launch ----
    wtsplit_kernel<<<ceil_div(D * HHc, 256), 256>>>(W1, wthi, wtlo, D, HHc);
    zero_f2<<<ceil_div(N * H1, 256), 256>>>(as1, ad1, N * H1);
    zero_f2<<<ceil_div(N, 256), 256>>>(as2, ad2, N);
    run_gemm((const __nv_bfloat16*)x, nullptr, wthi, wtlo, h1, N, D, HHc,
             a_src1, a_dst1, as1, ad1, H1, C1, 1);

    // ---- CSR build ----
    build_edges<<<ceil_div(ET, 256), 256>>>(eidx, E, N);
    zero_int<<<ceil_div(N, 256), 256>>>(cnt_p, N);
    hist_kernel<<<ceil_div(ET, 256), 256>>>(ET);
    int nb = ceil_div(N, 1024);
    scan1_kernel<<<nb, 1024>>>(N);
    scan2_kernel<<<1, 64>>>(nb);
    scan3_kernel<<<ceil_div(N, 256), 256>>>(N);
    copy_cursor<<<ceil_div(N, 256), 256>>>(N);
    scatter_kernel<<<ceil_div(ET, 256), 256>>>(ET);

    // ---- layer 1 aggregate (+PReLU, emits split bf16 for next GEMM) ----
    gat_aggregate<<<N, HHc / 4>>>(h1, as1, ad1, b1, nullptr, ahi, alo, H1, C1, 1, prelu_a);

    // ---- layer 2 ----
    wtsplit_kernel<<<ceil_div(HHc * M, 256), 256>>>(W2, wthi, wtlo, HHc, M);
    run_gemm(ahi, alo, wthi, wtlo, h2, N, HHc, M, a_src2, a_dst2, as2, ad2, 1, M, 0);
    zero_f2<<<ceil_div(N, 256), 256>>>(asd, add, N);
    gat_aggregate<<<N, M / 4>>>(h2, as2, ad2, b2, z, ahi, alo, 1, M, 0, prelu_a);

    // ---- decoder ----
    wtsplit_kernel<<<ceil_div(M * D, 256), 256>>>(Wd, wthi, wtlo, M, D);
    run_gemm(ahi, alo, wthi, wtlo, hd, N, M, D, a_srcd, a_dstd, asd, add, 1, D, 0);
    gat_aggregate<<<N, D / 4>>>(hd, asd, add, bd, x_hat, nullptr, nullptr, 1, D, 0, prelu_a);
}

// round 16
// speedup vs baseline: 1.1479x; 1.1479x over previous
#include <cuda_runtime.h>
#include <cuda_bf16.h>
#include <cuda_fp16.h>
#include <math.h>
#include <stdint.h>

// ---------------- problem-size maxima ----------------
#define MAXN   50000
#define MAXE   400000
#define MAXET  (MAXE + MAXN)
#define MAXHC  512
#define MAXM   256

// ---------------- device scratch ----------------
__device__ int   g_src [MAXET];
__device__ int   g_dst [MAXET];
__device__ int   g_srcs[MAXET];
__device__ int   g_cnt [MAXN];
__device__ int   g_rp  [MAXN + 1];
__device__ int   g_cur [MAXN];
__device__ int   g_bsum[64];

__device__ float g_h1 [(size_t)MAXN * MAXHC];
__device__ float g_h2 [(size_t)MAXN * MAXM];
__device__ float g_hd [(size_t)MAXN * MAXM];
__device__ __half g_ahi[(size_t)MAXN * MAXHC];
__device__ __half g_alo[(size_t)MAXN * MAXHC];
__device__ __half g_wt [512 * 512];
__device__ float g_as1[(size_t)MAXN * 4], g_ad1[(size_t)MAXN * 4];
__device__ float g_as2[MAXN], g_ad2[MAXN];
__device__ float g_asd[MAXN], g_add[MAXN];

// ---------------- PTX helpers ----------------
__device__ __forceinline__ uint32_t smem_u32(const void* p) {
    uint32_t a;
    asm("{ .reg .u64 t; cvta.to.shared.u64 t, %1; cvt.u32.u64 %0, t; }" : "=r"(a) : "l"(p));
    return a;
}
__device__ __forceinline__ void ldmx4(uint32_t* r, uint32_t addr) {
    asm volatile("ldmatrix.sync.aligned.m8n8.x4.shared.b16 {%0,%1,%2,%3}, [%4];"
        : "=r"(r[0]), "=r"(r[1]), "=r"(r[2]), "=r"(r[3]) : "r"(addr));
}
__device__ __forceinline__ void mma16816(float* c, const uint32_t* a,
                                         uint32_t b0, uint32_t b1) {
    asm volatile(
        "mma.sync.aligned.m16n8k16.row.col.f32.f16.f16.f32 "
        "{%0,%1,%2,%3}, {%4,%5,%6,%7}, {%8,%9}, {%0,%1,%2,%3};"
        : "+f"(c[0]), "+f"(c[1]), "+f"(c[2]), "+f"(c[3])
        : "r"(a[0]), "r"(a[1]), "r"(a[2]), "r"(a[3]), "r"(b0), "r"(b1));
}
// 8 fp32 (two uint4) -> fp16 hi/lo split packed as two uint4 (8 halves each)
__device__ __forceinline__ void cvt8h(uint4 r0, uint4 r1, uint4& h, uint4& l) {
    float v[8];
    *(uint4*)&v[0] = r0; *(uint4*)&v[4] = r1;
    __half2 hh[4], ll[4];
#pragma unroll
    for (int i = 0; i < 4; i++) {
        __half a = __float2half_rn(v[2 * i]);
        __half b = __float2half_rn(v[2 * i + 1]);
        hh[i].x = a; hh[i].y = b;
        ll[i].x = __float2half_rn(v[2 * i]     - __half2float(a));
        ll[i].y = __float2half_rn(v[2 * i + 1] - __half2float(b));
    }
    h = *(uint4*)hh; l = *(uint4*)ll;
}

// ---------------- graph-building kernels ----------------
__global__ void build_edges(const void* __restrict__ ei, int E, int Nn) {
    __shared__ int s_is64;
    if (threadIdx.x == 0) {
        const int* p = (const int*)ei;
        int nz = 0;
        int cnt = E < 64 ? E : 64;
        for (int i = 0; i < cnt; i++) nz |= p[2 * i + 1];
        s_is64 = (nz == 0) ? 1 : 0;
    }
    __syncthreads();
    int i = blockIdx.x * blockDim.x + threadIdx.x;
    int tot = E + Nn;
    if (i >= tot) return;
    int s, d;
    if (i < E) {
        if (s_is64) {
            const long long* p = (const long long*)ei;
            s = (int)p[i]; d = (int)p[E + i];
        } else {
            const int* p = (const int*)ei;
            s = p[i]; d = p[E + i];
        }
    } else { s = d = i - E; }
    g_src[i] = s; g_dst[i] = d;
}
__global__ void zero_int(int* p, int n) {
    int i = blockIdx.x * blockDim.x + threadIdx.x;
    if (i < n) p[i] = 0;
}
__global__ void zero_f2(float* a, float* b, int n) {
    int i = blockIdx.x * blockDim.x + threadIdx.x;
    if (i < n) { a[i] = 0.f; b[i] = 0.f; }
}
__global__ void hist_kernel(int tot) {
    int i = blockIdx.x * blockDim.x + threadIdx.x;
    if (i < tot) atomicAdd(&g_cnt[g_dst[i]], 1);
}
__global__ void scan1_kernel(int n) {
    __shared__ int sh[1024];
    int tx = threadIdx.x;
    int i = blockIdx.x * 1024 + tx;
    int v = (i < n) ? g_cnt[i] : 0;
    sh[tx] = v;
    __syncthreads();
    for (int off = 1; off < 1024; off <<= 1) {
        int t = (tx >= off) ? sh[tx - off] : 0;
        __syncthreads();
        sh[tx] += t;
        __syncthreads();
    }
    if (i < n) g_rp[i + 1] = sh[tx];
    if (tx == 1023) g_bsum[blockIdx.x] = sh[1023];
}
__global__ void scan2_kernel(int nb) {
    __shared__ int sh[64];
    int tx = threadIdx.x;
    int v = (tx < nb) ? g_bsum[tx] : 0;
    sh[tx] = v;
    __syncthreads();
    for (int off = 1; off < 64; off <<= 1) {
        int t = (tx >= off) ? sh[tx - off] : 0;
        __syncthreads();
        sh[tx] += t;
        __syncthreads();
    }
    if (tx < nb) g_bsum[tx] = sh[tx];
}
__global__ void scan3_kernel(int n) {
    int i = blockIdx.x * blockDim.x + threadIdx.x;
    if (i == 0) g_rp[0] = 0;
    if (i < n) {
        int b = i >> 10;
        if (b > 0) g_rp[i + 1] += g_bsum[b - 1];
    }
}
__global__ void copy_cursor(int n) {
    int i = blockIdx.x * blockDim.x + threadIdx.x;
    if (i < n) g_cur[i] = g_rp[i];
}
__global__ void scatter_kernel(int tot) {
    int i = blockIdx.x * blockDim.x + threadIdx.x;
    if (i >= tot) return;
    int d = g_dst[i];
    int pos = atomicAdd(&g_cur[d], 1);
    g_srcs[pos] = g_src[i];
}

// ---------------- fp16 convert of W^T (single rounding) ----------------
__global__ void wtcvt_kernel(const float* __restrict__ W,
                             __half* __restrict__ wt, int K, int N) {
    int idx = blockIdx.x * blockDim.x + threadIdx.x;
    if (idx >= K * N) return;
    int k = idx / N, n = idx - k * N;
    wt[(size_t)n * K + k] = __float2half_rn(W[idx]);
}

// ---------------- fp16-split tensor-core GEMM + fused alpha epilogue ---------
// C[M,N] = A[M,K] @ (Bf[N,K])^T, fp32 accumulate.
// A = Ahi + Alo (fp16 2-way split; from presplit buffers or raw fp32 in-kernel).
// B = Bf (single fp16 rounding). 2 MMAs per k-step: Ahi*Bf + Alo*Bf.
// CTA tile 128x64, BK=32, 8 warps (4M x 2N), warp tile 32x32.
__global__ void __launch_bounds__(256, 2)
mma_gemm(const __half* __restrict__ Ahi, const __half* __restrict__ Alo,
         const __half* __restrict__ Bf,
         float* __restrict__ C, int M, int K, int N,
         const float* __restrict__ asrc, const float* __restrict__ adst,
         float* __restrict__ as_, float* __restrict__ ad_, int H, int Ch,
         int a_fp32) {
    __shared__ __align__(16) uint8_t sAh[128 * 80], sAl[128 * 80];
    __shared__ __align__(16) uint8_t sB [64 * 80];
    int tid = threadIdx.x, lane = tid & 31, wid = tid >> 5;
    int wm = wid & 3, wn = wid >> 2;
    int m0 = blockIdx.y * 128, n0 = blockIdx.x * 64;

    int lr = tid >> 2, lc = tid & 3;
    int gm0 = m0 + lr, gm1 = m0 + lr + 64;
    const size_t a0off = (size_t)gm0 * K + lc * 8;
    const size_t a1off = (size_t)gm1 * K + lc * 8;
    const size_t bOff  = (size_t)(n0 + lr) * K + lc * 8;
    uint32_t stA0 = (uint32_t)(lr * 80 + lc * 16);
    uint32_t stA1 = (uint32_t)((lr + 64) * 80 + lc * 16);
    const float* X = (const float*)Ahi;   // when a_fp32

    uint32_t sAhB = smem_u32(sAh), sAlB = smem_u32(sAl), sBB = smem_u32(sB);

    uint32_t aoffs[2], boffs[2];
#pragma unroll
    for (int mt = 0; mt < 2; mt++)
        aoffs[mt] = (uint32_t)((wm * 32 + mt * 16 + (lane & 15)) * 80 + (lane >> 4) * 16);
#pragma unroll
    for (int p = 0; p < 2; p++)
        boffs[p] = (uint32_t)((wn * 32 + p * 16 + ((lane >> 3) & 1) * 8 + (lane & 7)) * 80
                              + (lane >> 4) * 16);

    float acc[2][4][4];
#pragma unroll
    for (int i = 0; i < 2; i++)
#pragma unroll
        for (int j = 0; j < 4; j++)
#pragma unroll
            for (int q = 0; q < 4; q++) acc[i][j][q] = 0.f;

    const uint4 z4 = make_uint4(0, 0, 0, 0);
    uint4 pa0h, pa1h, pa0l, pa1l, pb;
    if (a_fp32) {
        const uint4* p0 = (const uint4*)(X + a0off);
        const uint4* p1 = (const uint4*)(X + a1off);
        pa0h = (gm0 < M) ? p0[0] : z4;  pa0l = (gm0 < M) ? p0[1] : z4;
        pa1h = (gm1 < M) ? p1[0] : z4;  pa1l = (gm1 < M) ? p1[1] : z4;
    } else {
        pa0h = (gm0 < M) ? *(const uint4*)(Ahi + a0off) : z4;
        pa1h = (gm1 < M) ? *(const uint4*)(Ahi + a1off) : z4;
        pa0l = (gm0 < M) ? *(const uint4*)(Alo + a0off) : z4;
        pa1l = (gm1 < M) ? *(const uint4*)(Alo + a1off) : z4;
    }
    pb = *(const uint4*)(Bf + bOff);

    int nch = K >> 5;
    for (int ch = 0; ch < nch; ch++) {
        if (a_fp32) {
            uint4 h0, l0, h1, l1;
            cvt8h(pa0h, pa0l, h0, l0);
            cvt8h(pa1h, pa1l, h1, l1);
            *(uint4*)(sAh + stA0) = h0;
            *(uint4*)(sAl + stA0) = l0;
            *(uint4*)(sAh + stA1) = h1;
            *(uint4*)(sAl + stA1) = l1;
        } else {
            *(uint4*)(sAh + stA0) = pa0h;
            *(uint4*)(sAh + stA1) = pa1h;
            *(uint4*)(sAl + stA0) = pa0l;
            *(uint4*)(sAl + stA1) = pa1l;
        }
        *(uint4*)(sB + stA0) = pb;
        __syncthreads();

        if (ch + 1 < nch) {
            int k8 = (ch + 1) * 32;
            if (a_fp32) {
                const uint4* p0 = (const uint4*)(X + a0off + k8);
                const uint4* p1 = (const uint4*)(X + a1off + k8);
                pa0h = (gm0 < M) ? p0[0] : z4;  pa0l = (gm0 < M) ? p0[1] : z4;
                pa1h = (gm1 < M) ? p1[0] : z4;  pa1l = (gm1 < M) ? p1[1] : z4;
            } else {
                pa0h = (gm0 < M) ? *(const uint4*)(Ahi + a0off + k8) : z4;
                pa1h = (gm1 < M) ? *(const uint4*)(Ahi + a1off + k8) : z4;
                pa0l = (gm0 < M) ? *(const uint4*)(Alo + a0off + k8) : z4;
                pa1l = (gm1 < M) ? *(const uint4*)(Alo + a1off + k8) : z4;
            }
            pb = *(const uint4*)(Bf + bOff + k8);
        }

#pragma unroll
        for (int ks = 0; ks < 2; ks++) {
            uint32_t AH[2][4], AL[2][4], BB[2][4];
            ldmx4(AH[0], sAhB + aoffs[0] + ks * 32);
            ldmx4(AH[1], sAhB + aoffs[1] + ks * 32);
            ldmx4(AL[0], sAlB + aoffs[0] + ks * 32);
            ldmx4(AL[1], sAlB + aoffs[1] + ks * 32);
            ldmx4(BB[0], sBB + boffs[0] + ks * 32);
            ldmx4(BB[1], sBB + boffs[1] + ks * 32);
            // term 1: Ahi x Bf (8 independent accumulators)
#pragma unroll
            for (int mt = 0; mt < 2; mt++)
#pragma unroll
                for (int p = 0; p < 2; p++) {
                    mma16816(acc[mt][p * 2 + 0], AH[mt], BB[p][0], BB[p][2]);
                    mma16816(acc[mt][p * 2 + 1], AH[mt], BB[p][1], BB[p][3]);
                }
            // term 2: Alo x Bf
#pragma unroll
            for (int mt = 0; mt < 2; mt++)
#pragma unroll
                for (int p = 0; p < 2; p++) {
                    mma16816(acc[mt][p * 2 + 0], AL[mt], BB[p][0], BB[p][2]);
                    mma16816(acc[mt][p * 2 + 1], AL[mt], BB[p][1], BB[p][3]);
                }
        }
        __syncthreads();
    }

    // ---- epilogue: store C + fused alpha partials ----
    int hh = n0 / Ch;
#pragma unroll
    for (int mt = 0; mt < 2; mt++) {
        int gr0 = m0 + wm * 32 + mt * 16 + (lane >> 2);
        int gr1 = gr0 + 8;
        float ps0 = 0.f, pd0 = 0.f, ps1 = 0.f, pd1 = 0.f;
#pragma unroll
        for (int nt = 0; nt < 4; nt++) {
            int gc = n0 + wn * 32 + nt * 8 + (lane & 3) * 2;
            float a0 = asrc[gc], a1 = asrc[gc + 1];
            float d0 = adst[gc], d1 = adst[gc + 1];
            ps0 = fmaf(acc[mt][nt][0], a0, fmaf(acc[mt][nt][1], a1, ps0));
            pd0 = fmaf(acc[mt][nt][0], d0, fmaf(acc[mt][nt][1], d1, pd0));
            ps1 = fmaf(acc[mt][nt][2], a0, fmaf(acc[mt][nt][3], a1, ps1));
            pd1 = fmaf(acc[mt][nt][2], d0, fmaf(acc[mt][nt][3], d1, pd1));
            if (gr0 < M)
                *(float2*)(C + (size_t)gr0 * N + gc) = make_float2(acc[mt][nt][0], acc[mt][nt][1]);
            if (gr1 < M)
                *(float2*)(C + (size_t)gr1 * N + gc) = make_float2(acc[mt][nt][2], acc[mt][nt][3]);
        }
#pragma unroll
        for (int o = 1; o <= 2; o <<= 1) {
            ps0 += __shfl_xor_sync(0xffffffffu, ps0, o);
            pd0 += __shfl_xor_sync(0xffffffffu, pd0, o);
            ps1 += __shfl_xor_sync(0xffffffffu, ps1, o);
            pd1 += __shfl_xor_sync(0xffffffffu, pd1, o);
        }
        if ((lane & 3) == 0) {
            if (gr0 < M) {
                atomicAdd(&as_[(size_t)gr0 * H + hh], ps0);
                atomicAdd(&ad_[(size_t)gr0 * H + hh], pd0);
            }
            if (gr1 < M) {
                atomicAdd(&as_[(size_t)gr1 * H + hh], ps1);
                atomicAdd(&ad_[(size_t)gr1 * H + hh], pd1);
            }
        }
    }
}

// ---------------- GAT segment-softmax + aggregate (float4 channels) ----------
#define CHUNK 64
__global__ void gat_aggregate(const float* __restrict__ feat,
                              const float* __restrict__ as_,
                              const float* __restrict__ ad_,
                              const float* __restrict__ bias,
                              float* __restrict__ out,            // nullable
                              __half* __restrict__ ohi,           // nullable
                              __half* __restrict__ olo,
                              int H, int C, int prelu,
                              const float* __restrict__ prelu_a) {
    int n = blockIdx.x;
    int t = threadIdx.x;
    int HC = H * C;
    int t4 = t * 4;
    int h = t4 / C;
    __shared__ float sw[4 * CHUNK];
    __shared__ int   ssrc[CHUNK];
    int s0 = g_rp[n], s1 = g_rp[n + 1];
    int warp = t >> 5, lane = t & 31;

    float m = 0.f, rdn = 0.f, ad = 0.f;
    if (warp < H) {
        ad = ad_[(size_t)n * H + warp];
        m = -INFINITY;
        for (int k = s0 + lane; k < s1; k += 32) {
            float e = as_[(size_t)g_srcs[k] * H + warp] + ad;
            e = e > 0.f ? e : 0.2f * e;
            m = fmaxf(m, e);
        }
#pragma unroll
        for (int o = 16; o; o >>= 1) m = fmaxf(m, __shfl_xor_sync(0xffffffffu, m, o));
        float ds = 0.f;
        for (int k = s0 + lane; k < s1; k += 32) {
            float e = as_[(size_t)g_srcs[k] * H + warp] + ad;
            e = e > 0.f ? e : 0.2f * e;
            ds += __expf(e - m);
        }
#pragma unroll
        for (int o = 16; o; o >>= 1) ds += __shfl_xor_sync(0xffffffffu, ds, o);
        rdn = 1.f / (ds + 1e-16f);
    }

    float4 acc = make_float4(0.f, 0.f, 0.f, 0.f);
    for (int base = s0; base < s1; base += CHUNK) {
        int count = min(CHUNK, s1 - base);
        __syncthreads();
        if (warp < H) {
            for (int j = lane; j < count; j += 32) {
                int s = g_srcs[base + j];
                if (warp == 0) ssrc[j] = s;
                float e = as_[(size_t)s * H + warp] + ad;
                e = e > 0.f ? e : 0.2f * e;
                sw[warp * CHUNK + j] = __expf(e - m) * rdn;
            }
        }
        __syncthreads();
        const float* swh = sw + h * CHUNK;
        for (int j = 0; j < count; j++) {
            float4 f = *(const float4*)(feat + (size_t)ssrc[j] * HC + t4);
            float w = swh[j];
            acc.x = fmaf(f.x, w, acc.x);
            acc.y = fmaf(f.y, w, acc.y);
            acc.z = fmaf(f.z, w, acc.z);
            acc.w = fmaf(f.w, w, acc.w);
        }
    }

    float4 b4 = *(const float4*)(bias + t4);
    float v0 = acc.x + b4.x, v1 = acc.y + b4.y, v2 = acc.z + b4.z, v3 = acc.w + b4.w;
    if (prelu) {
        float a = prelu_a[0];
        v0 = v0 >= 0.f ? v0 : a * v0;
        v1 = v1 >= 0.f ? v1 : a * v1;
        v2 = v2 >= 0.f ? v2 : a * v2;
        v3 = v3 >= 0.f ? v3 : a * v3;
    }
    size_t idx = (size_t)n * HC + t4;
    if (out) {
        *(float4*)(out + idx) = make_float4(v0, v1, v2, v3);
    }
    if (ohi) {
        __half h0 = __float2half_rn(v0);
        __half h1 = __float2half_rn(v1);
        __half h2 = __float2half_rn(v2);
        __half h3 = __float2half_rn(v3);
        __half2 hh01; hh01.x = h0; hh01.y = h1;
        __half2 hh23; hh23.x = h2; hh23.y = h3;
        *(__half2*)(ohi + idx)     = hh01;
        *(__half2*)(ohi + idx + 2) = hh23;
        __half2 ll01;
        ll01.x = __float2half_rn(v0 - __half2float(h0));
        ll01.y = __float2half_rn(v1 - __half2float(h1));
        __half2 ll23;
        ll23.x = __float2half_rn(v2 - __half2float(h2));
        ll23.y = __float2half_rn(v3 - __half2float(h3));
        *(__half2*)(olo + idx)     = ll01;
        *(__half2*)(olo + idx + 2) = ll23;
    }
}

// ---------------- host orchestration ----------------
static inline int ceil_div(int a, int b) { return (a + b - 1) / b; }

static void run_gemm(const __half* Ahi, const __half* Alo, const __half* Bf,
                     float* C, int M, int K, int N,
                     const float* asrc, const float* adst,
                     float* as_, float* ad_, int H, int Ch, int a_fp32) {
    dim3 grid(N / 64, ceil_div(M, 128));
    mma_gemm<<<grid, 256>>>(Ahi, Alo, Bf, C, M, K, N,
                            asrc, adst, as_, ad_, H, Ch, a_fp32);
}

extern "C" void kernel_launch(void* const* d_in, const int* in_sizes, int n_in,
                              void* d_out, int out_size) {
    const float* x       = (const float*)d_in[0];
    const void*  eidx    = d_in[1];
    const float* W1      = (const float*)d_in[2];
    const float* a_src1  = (const float*)d_in[3];
    const float* a_dst1  = (const float*)d_in[4];
    const float* b1      = (const float*)d_in[5];
    const float* prelu_a = (const float*)d_in[6];
    const float* W2      = (const float*)d_in[7];
    const float* a_src2  = (const float*)d_in[8];
    const float* a_dst2  = (const float*)d_in[9];
    const float* b2      = (const float*)d_in[10];
    const float* Wd      = (const float*)d_in[11];
    const float* a_srcd  = (const float*)d_in[12];
    const float* a_dstd  = (const float*)d_in[13];
    const float* bd      = (const float*)d_in[14];

    const int HHc = in_sizes[3];          // 512
    const int H1  = 4;
    const int C1  = HHc / H1;             // 128
    const int M   = in_sizes[8];          // 256
    const int D   = in_sizes[12];         // 256
    const int N   = in_sizes[0] / D;      // 50000
    const int E   = in_sizes[1] / 2;      // 400000
    const int ET  = E + N;

    float* out   = (float*)d_out;
    float* z     = out;
    float* x_hat = out + (size_t)N * M;

    float *h1, *h2, *hd;
    float *as1, *ad1, *as2, *ad2, *asd, *add;
    __half *ahi, *alo, *wt;
    int *cnt_p;
    cudaGetSymbolAddress((void**)&h1,  g_h1);
    cudaGetSymbolAddress((void**)&h2,  g_h2);
    cudaGetSymbolAddress((void**)&hd,  g_hd);
    cudaGetSymbolAddress((void**)&ahi, g_ahi);
    cudaGetSymbolAddress((void**)&alo, g_alo);
    cudaGetSymbolAddress((void**)&wt,  g_wt);
    cudaGetSymbolAddress((void**)&as1, g_as1);
    cudaGetSymbolAddress((void**)&ad1, g_ad1);
    cudaGetSymbolAddress((void**)&as2, g_as2);
    cudaGetSymbolAddress((void**)&ad2, g_ad2);
    cudaGetSymbolAddress((void**)&asd, g_asd);
    cudaGetSymbolAddress((void**)&add, g_add);
    cudaGetSymbolAddress((void**)&cnt_p, g_cnt);

    // ---- layer 1 GEMM (x split fused in-kernel); gemm1 stays 4th launch ----
    wtcvt_kernel<<<ceil_div(D * HHc, 256), 256>>>(W1, wt, D, HHc);
    zero_f2<<<ceil_div(N * H1, 256), 256>>>(as1, ad1, N * H1);
    zero_f2<<<ceil_div(N, 256), 256>>>(as2, ad2, N);
    run_gemm((const __half*)x, nullptr, wt, h1, N, D, HHc,
             a_src1, a_dst1, as1, ad1, H1, C1, 1);

    // ---- CSR build ----
    build_edges<<<ceil_div(ET, 256), 256>>>(eidx, E, N);
    zero_int<<<ceil_div(N, 256), 256>>>(cnt_p, N);
    hist_kernel<<<ceil_div(ET, 256), 256>>>(ET);
    int nb = ceil_div(N, 1024);
    scan1_kernel<<<nb, 1024>>>(N);
    scan2_kernel<<<1, 64>>>(nb);
    scan3_kernel<<<ceil_div(N, 256), 256>>>(N);
    copy_cursor<<<ceil_div(N, 256), 256>>>(N);
    scatter_kernel<<<ceil_div(ET, 256), 256>>>(ET);

    // ---- layer 1 aggregate (+PReLU, emits fp16 split for next GEMM) ----
    gat_aggregate<<<N, HHc / 4>>>(h1, as1, ad1, b1, nullptr, ahi, alo, H1, C1, 1, prelu_a);

    // ---- layer 2 ----
    wtcvt_kernel<<<ceil_div(HHc * M, 256), 256>>>(W2, wt, HHc, M);
    run_gemm(ahi, alo, wt, h2, N, HHc, M, a_src2, a_dst2, as2, ad2, 1, M, 0);
    zero_f2<<<ceil_div(N, 256), 256>>>(asd, add, N);
    gat_aggregate<<<N, M / 4>>>(h2, as2, ad2, b2, z, ahi, alo, 1, M, 0, prelu_a);

    // ---- decoder ----
    wtcvt_kernel<<<ceil_div(M * D, 256), 256>>>(Wd, wt, M, D);
    run_gemm(ahi, alo, wt, hd, N, M, D, a_srcd, a_dstd, asd, add, 1, D, 0);
    gat_aggregate<<<N, D / 4>>>(hd, asd, add, bd, x_hat, nullptr, nullptr, 1, D, 0, prelu_a);
}

// round 17
// speedup vs baseline: 1.1864x; 1.0336x over previous
#include <cuda_runtime.h>
#include <cuda_bf16.h>
#include <cuda_fp16.h>
#include <math.h>
#include <stdint.h>

// ---------------- problem-size maxima ----------------
#define MAXN   50000
#define MAXE   400000
#define MAXET  (MAXE + MAXN)
#define MAXHC  512
#define MAXM   256

// ---------------- device scratch ----------------
__device__ int   g_src [MAXET];
__device__ int   g_dst [MAXET];
__device__ int   g_srcs[MAXET];
__device__ int   g_cnt [MAXN];
__device__ int   g_rp  [MAXN + 1];
__device__ int   g_cur [MAXN];
__device__ int   g_bsum[64];

__device__ float g_h1 [(size_t)MAXN * MAXHC];
__device__ float g_h2 [(size_t)MAXN * MAXM];
__device__ float g_hd [(size_t)MAXN * MAXM];
__device__ __half g_ahi[(size_t)MAXN * MAXHC];
__device__ __half g_alo[(size_t)MAXN * MAXHC];
__device__ __half g_wt [512 * 512];
__device__ float g_as1[(size_t)MAXN * 4], g_ad1[(size_t)MAXN * 4];
__device__ float g_as2[MAXN], g_ad2[MAXN];
__device__ float g_asd[MAXN], g_add[MAXN];

// ---------------- PTX helpers ----------------
__device__ __forceinline__ uint32_t smem_u32(const void* p) {
    uint32_t a;
    asm("{ .reg .u64 t; cvta.to.shared.u64 t, %1; cvt.u32.u64 %0, t; }" : "=r"(a) : "l"(p));
    return a;
}
__device__ __forceinline__ void ldmx4(uint32_t* r, uint32_t addr) {
    asm volatile("ldmatrix.sync.aligned.m8n8.x4.shared.b16 {%0,%1,%2,%3}, [%4];"
        : "=r"(r[0]), "=r"(r[1]), "=r"(r[2]), "=r"(r[3]) : "r"(addr));
}
__device__ __forceinline__ void mma16816(float* c, const uint32_t* a,
                                         uint32_t b0, uint32_t b1) {
    asm volatile(
        "mma.sync.aligned.m16n8k16.row.col.f32.f16.f16.f32 "
        "{%0,%1,%2,%3}, {%4,%5,%6,%7}, {%8,%9}, {%0,%1,%2,%3};"
        : "+f"(c[0]), "+f"(c[1]), "+f"(c[2]), "+f"(c[3])
        : "r"(a[0]), "r"(a[1]), "r"(a[2]), "r"(a[3]), "r"(b0), "r"(b1));
}
// 8 fp32 (two uint4) -> fp16 hi/lo split packed as two uint4 (8 halves each)
__device__ __forceinline__ void cvt8h(uint4 r0, uint4 r1, uint4& h, uint4& l) {
    float v[8];
    *(uint4*)&v[0] = r0; *(uint4*)&v[4] = r1;
    __half2 hh[4], ll[4];
#pragma unroll
    for (int i = 0; i < 4; i++) {
        __half a = __float2half_rn(v[2 * i]);
        __half b = __float2half_rn(v[2 * i + 1]);
        hh[i].x = a; hh[i].y = b;
        ll[i].x = __float2half_rn(v[2 * i]     - __half2float(a));
        ll[i].y = __float2half_rn(v[2 * i + 1] - __half2float(b));
    }
    h = *(uint4*)hh; l = *(uint4*)ll;
}

// ---------------- graph-building kernels ----------------
__global__ void build_edges(const void* __restrict__ ei, int E, int Nn) {
    __shared__ int s_is64;
    if (threadIdx.x == 0) {
        const int* p = (const int*)ei;
        int nz = 0;
        int cnt = E < 64 ? E : 64;
        for (int i = 0; i < cnt; i++) nz |= p[2 * i + 1];
        s_is64 = (nz == 0) ? 1 : 0;
    }
    __syncthreads();
    int i = blockIdx.x * blockDim.x + threadIdx.x;
    int tot = E + Nn;
    if (i >= tot) return;
    int s, d;
    if (i < E) {
        if (s_is64) {
            const long long* p = (const long long*)ei;
            s = (int)p[i]; d = (int)p[E + i];
        } else {
            const int* p = (const int*)ei;
            s = p[i]; d = p[E + i];
        }
    } else { s = d = i - E; }
    g_src[i] = s; g_dst[i] = d;
}
__global__ void zero_int(int* p, int n) {
    int i = blockIdx.x * blockDim.x + threadIdx.x;
    if (i < n) p[i] = 0;
}
__global__ void zero_f2(float* a, float* b, int n) {
    int i = blockIdx.x * blockDim.x + threadIdx.x;
    if (i < n) { a[i] = 0.f; b[i] = 0.f; }
}
__global__ void hist_kernel(int tot) {
    int i = blockIdx.x * blockDim.x + threadIdx.x;
    if (i < tot) atomicAdd(&g_cnt[g_dst[i]], 1);
}
__global__ void scan1_kernel(int n) {
    __shared__ int sh[1024];
    int tx = threadIdx.x;
    int i = blockIdx.x * 1024 + tx;
    int v = (i < n) ? g_cnt[i] : 0;
    sh[tx] = v;
    __syncthreads();
    for (int off = 1; off < 1024; off <<= 1) {
        int t = (tx >= off) ? sh[tx - off] : 0;
        __syncthreads();
        sh[tx] += t;
        __syncthreads();
    }
    if (i < n) g_rp[i + 1] = sh[tx];
    if (tx == 1023) g_bsum[blockIdx.x] = sh[1023];
}
__global__ void scan2_kernel(int nb) {
    __shared__ int sh[64];
    int tx = threadIdx.x;
    int v = (tx < nb) ? g_bsum[tx] : 0;
    sh[tx] = v;
    __syncthreads();
    for (int off = 1; off < 64; off <<= 1) {
        int t = (tx >= off) ? sh[tx - off] : 0;
        __syncthreads();
        sh[tx] += t;
        __syncthreads();
    }
    if (tx < nb) g_bsum[tx] = sh[tx];
}
__global__ void scan3_kernel(int n) {
    int i = blockIdx.x * blockDim.x + threadIdx.x;
    if (i == 0) g_rp[0] = 0;
    if (i < n) {
        int b = i >> 10;
        if (b > 0) g_rp[i + 1] += g_bsum[b - 1];
    }
}
__global__ void copy_cursor(int n) {
    int i = blockIdx.x * blockDim.x + threadIdx.x;
    if (i < n) g_cur[i] = g_rp[i];
}
__global__ void scatter_kernel(int tot) {
    int i = blockIdx.x * blockDim.x + threadIdx.x;
    if (i >= tot) return;
    int d = g_dst[i];
    int pos = atomicAdd(&g_cur[d], 1);
    g_srcs[pos] = g_src[i];
}

// ---------------- fp16 convert of W^T (single rounding) ----------------
__global__ void wtcvt_kernel(const float* __restrict__ W,
                             __half* __restrict__ wt, int K, int N) {
    int idx = blockIdx.x * blockDim.x + threadIdx.x;
    if (idx >= K * N) return;
    int k = idx / N, n = idx - k * N;
    wt[(size_t)n * K + k] = __float2half_rn(W[idx]);
}

// ---------------- fp16-split tensor-core GEMM, wide warp tile ----------------
// C[M,N] = A[M,K] @ (Bf[N,K])^T, fp32 accumulate.
// A = Ahi + Alo (fp16 2-way split; presplit or raw fp32 split in-kernel).
// CTA tile 128x128, BK=32, 8 warps (4M x 2N), warp tile 32x64.
// Epilogue fuses alpha_s/alpha_d (as_/ad_ zeroed before launch).
__global__ void __launch_bounds__(256, 2)
mma_gemm(const __half* __restrict__ Ahi, const __half* __restrict__ Alo,
         const __half* __restrict__ Bf,
         float* __restrict__ C, int M, int K, int N,
         const float* __restrict__ asrc, const float* __restrict__ adst,
         float* __restrict__ as_, float* __restrict__ ad_, int H, int Ch,
         int a_fp32) {
    __shared__ __align__(16) uint8_t sAh[128 * 80], sAl[128 * 80];
    __shared__ __align__(16) uint8_t sB [128 * 80];
    int tid = threadIdx.x, lane = tid & 31, wid = tid >> 5;
    int wm = wid & 3, wn = wid >> 2;
    int m0 = blockIdx.y * 128, n0 = blockIdx.x * 128;

    int lr = tid >> 2, lc = tid & 3;
    int gm0 = m0 + lr, gm1 = m0 + lr + 64;
    const size_t a0off = (size_t)gm0 * K + lc * 8;
    const size_t a1off = (size_t)gm1 * K + lc * 8;
    const size_t b0off = (size_t)(n0 + lr) * K + lc * 8;
    const size_t b1off = (size_t)(n0 + lr + 64) * K + lc * 8;
    uint32_t stA0 = (uint32_t)(lr * 80 + lc * 16);
    uint32_t stA1 = (uint32_t)((lr + 64) * 80 + lc * 16);
    const float* X = (const float*)Ahi;   // when a_fp32

    uint32_t sAhB = smem_u32(sAh), sAlB = smem_u32(sAl), sBB = smem_u32(sB);

    uint32_t aoffs[2], boffs[4];
#pragma unroll
    for (int mt = 0; mt < 2; mt++)
        aoffs[mt] = (uint32_t)((wm * 32 + mt * 16 + (lane & 15)) * 80 + (lane >> 4) * 16);
#pragma unroll
    for (int p = 0; p < 4; p++)
        boffs[p] = (uint32_t)((wn * 64 + p * 16 + ((lane >> 3) & 1) * 8 + (lane & 7)) * 80
                              + (lane >> 4) * 16);

    float acc[2][8][4];
#pragma unroll
    for (int i = 0; i < 2; i++)
#pragma unroll
        for (int j = 0; j < 8; j++)
#pragma unroll
            for (int q = 0; q < 4; q++) acc[i][j][q] = 0.f;

    const uint4 z4 = make_uint4(0, 0, 0, 0);
    uint4 pa0h, pa1h, pa0l, pa1l, pb0, pb1;
    if (a_fp32) {
        const uint4* p0 = (const uint4*)(X + a0off);
        const uint4* p1 = (const uint4*)(X + a1off);
        pa0h = (gm0 < M) ? p0[0] : z4;  pa0l = (gm0 < M) ? p0[1] : z4;
        pa1h = (gm1 < M) ? p1[0] : z4;  pa1l = (gm1 < M) ? p1[1] : z4;
    } else {
        pa0h = (gm0 < M) ? *(const uint4*)(Ahi + a0off) : z4;
        pa1h = (gm1 < M) ? *(const uint4*)(Ahi + a1off) : z4;
        pa0l = (gm0 < M) ? *(const uint4*)(Alo + a0off) : z4;
        pa1l = (gm1 < M) ? *(const uint4*)(Alo + a1off) : z4;
    }
    pb0 = *(const uint4*)(Bf + b0off);
    pb1 = *(const uint4*)(Bf + b1off);

    int nch = K >> 5;
    for (int ch = 0; ch < nch; ch++) {
        if (a_fp32) {
            uint4 h0, l0, h1, l1;
            cvt8h(pa0h, pa0l, h0, l0);
            cvt8h(pa1h, pa1l, h1, l1);
            *(uint4*)(sAh + stA0) = h0;
            *(uint4*)(sAl + stA0) = l0;
            *(uint4*)(sAh + stA1) = h1;
            *(uint4*)(sAl + stA1) = l1;
        } else {
            *(uint4*)(sAh + stA0) = pa0h;
            *(uint4*)(sAh + stA1) = pa1h;
            *(uint4*)(sAl + stA0) = pa0l;
            *(uint4*)(sAl + stA1) = pa1l;
        }
        *(uint4*)(sB + stA0) = pb0;
        *(uint4*)(sB + stA1) = pb1;
        __syncthreads();

        if (ch + 1 < nch) {
            int k8 = (ch + 1) * 32;
            if (a_fp32) {
                const uint4* p0 = (const uint4*)(X + a0off + k8);
                const uint4* p1 = (const uint4*)(X + a1off + k8);
                pa0h = (gm0 < M) ? p0[0] : z4;  pa0l = (gm0 < M) ? p0[1] : z4;
                pa1h = (gm1 < M) ? p1[0] : z4;  pa1l = (gm1 < M) ? p1[1] : z4;
            } else {
                pa0h = (gm0 < M) ? *(const uint4*)(Ahi + a0off + k8) : z4;
                pa1h = (gm1 < M) ? *(const uint4*)(Ahi + a1off + k8) : z4;
                pa0l = (gm0 < M) ? *(const uint4*)(Alo + a0off + k8) : z4;
                pa1l = (gm1 < M) ? *(const uint4*)(Alo + a1off + k8) : z4;
            }
            pb0 = *(const uint4*)(Bf + b0off + k8);
            pb1 = *(const uint4*)(Bf + b1off + k8);
        }

#pragma unroll
        for (int ks = 0; ks < 2; ks++) {
            uint32_t AH[2][4], AL[2][4];
            ldmx4(AH[0], sAhB + aoffs[0] + ks * 32);
            ldmx4(AH[1], sAhB + aoffs[1] + ks * 32);
            ldmx4(AL[0], sAlB + aoffs[0] + ks * 32);
            ldmx4(AL[1], sAlB + aoffs[1] + ks * 32);
#pragma unroll
            for (int p = 0; p < 4; p++) {
                uint32_t BB[4];
                ldmx4(BB, sBB + boffs[p] + ks * 32);
#pragma unroll
                for (int mt = 0; mt < 2; mt++) {
                    mma16816(acc[mt][p * 2 + 0], AH[mt], BB[0], BB[2]);
                    mma16816(acc[mt][p * 2 + 1], AH[mt], BB[1], BB[3]);
                    mma16816(acc[mt][p * 2 + 0], AL[mt], BB[0], BB[2]);
                    mma16816(acc[mt][p * 2 + 1], AL[mt], BB[1], BB[3]);
                }
            }
        }
        __syncthreads();
    }

    // ---- epilogue: store C + fused alpha partials ----
    int hh = n0 / Ch;   // 128-wide n-tile lies within one head (Ch>=128)
#pragma unroll
    for (int mt = 0; mt < 2; mt++) {
        int gr0 = m0 + wm * 32 + mt * 16 + (lane >> 2);
        int gr1 = gr0 + 8;
        float ps0 = 0.f, pd0 = 0.f, ps1 = 0.f, pd1 = 0.f;
#pragma unroll
        for (int nt = 0; nt < 8; nt++) {
            int gc = n0 + wn * 64 + nt * 8 + (lane & 3) * 2;
            float a0 = asrc[gc], a1 = asrc[gc + 1];
            float d0 = adst[gc], d1 = adst[gc + 1];
            ps0 = fmaf(acc[mt][nt][0], a0, fmaf(acc[mt][nt][1], a1, ps0));
            pd0 = fmaf(acc[mt][nt][0], d0, fmaf(acc[mt][nt][1], d1, pd0));
            ps1 = fmaf(acc[mt][nt][2], a0, fmaf(acc[mt][nt][3], a1, ps1));
            pd1 = fmaf(acc[mt][nt][2], d0, fmaf(acc[mt][nt][3], d1, pd1));
            if (gr0 < M)
                *(float2*)(C + (size_t)gr0 * N + gc) = make_float2(acc[mt][nt][0], acc[mt][nt][1]);
            if (gr1 < M)
                *(float2*)(C + (size_t)gr1 * N + gc) = make_float2(acc[mt][nt][2], acc[mt][nt][3]);
        }
#pragma unroll
        for (int o = 1; o <= 2; o <<= 1) {
            ps0 += __shfl_xor_sync(0xffffffffu, ps0, o);
            pd0 += __shfl_xor_sync(0xffffffffu, pd0, o);
            ps1 += __shfl_xor_sync(0xffffffffu, ps1, o);
            pd1 += __shfl_xor_sync(0xffffffffu, pd1, o);
        }
        if ((lane & 3) == 0) {
            if (gr0 < M) {
                atomicAdd(&as_[(size_t)gr0 * H + hh], ps0);
                atomicAdd(&ad_[(size_t)gr0 * H + hh], pd0);
            }
            if (gr1 < M) {
                atomicAdd(&as_[(size_t)gr1 * H + hh], ps1);
                atomicAdd(&ad_[(size_t)gr1 * H + hh], pd1);
            }
        }
    }
}

// ---------------- GAT segment-softmax + aggregate (float4 channels) ----------
#define CHUNK 64
__global__ void gat_aggregate(const float* __restrict__ feat,
                              const float* __restrict__ as_,
                              const float* __restrict__ ad_,
                              const float* __restrict__ bias,
                              float* __restrict__ out,            // nullable
                              __half* __restrict__ ohi,           // nullable
                              __half* __restrict__ olo,
                              int H, int C, int prelu,
                              const float* __restrict__ prelu_a) {
    int n = blockIdx.x;
    int t = threadIdx.x;
    int HC = H * C;
    int t4 = t * 4;
    int h = t4 / C;
    __shared__ float sw[4 * CHUNK];
    __shared__ int   ssrc[CHUNK];
    int s0 = g_rp[n], s1 = g_rp[n + 1];
    int warp = t >> 5, lane = t & 31;

    float m = 0.f, rdn = 0.f, ad = 0.f;
    if (warp < H) {
        ad = ad_[(size_t)n * H + warp];
        m = -INFINITY;
        for (int k = s0 + lane; k < s1; k += 32) {
            float e = as_[(size_t)g_srcs[k] * H + warp] + ad;
            e = e > 0.f ? e : 0.2f * e;
            m = fmaxf(m, e);
        }
#pragma unroll
        for (int o = 16; o; o >>= 1) m = fmaxf(m, __shfl_xor_sync(0xffffffffu, m, o));
        float ds = 0.f;
        for (int k = s0 + lane; k < s1; k += 32) {
            float e = as_[(size_t)g_srcs[k] * H + warp] + ad;
            e = e > 0.f ? e : 0.2f * e;
            ds += __expf(e - m);
        }
#pragma unroll
        for (int o = 16; o; o >>= 1) ds += __shfl_xor_sync(0xffffffffu, ds, o);
        rdn = 1.f / (ds + 1e-16f);
    }

    float4 acc = make_float4(0.f, 0.f, 0.f, 0.f);
    for (int base = s0; base < s1; base += CHUNK) {
        int count = min(CHUNK, s1 - base);
        __syncthreads();
        if (warp < H) {
            for (int j = lane; j < count; j += 32) {
                int s = g_srcs[base + j];
                if (warp == 0) ssrc[j] = s;
                float e = as_[(size_t)s * H + warp] + ad;
                e = e > 0.f ? e : 0.2f * e;
                sw[warp * CHUNK + j] = __expf(e - m) * rdn;
            }
        }
        __syncthreads();
        const float* swh = sw + h * CHUNK;
        for (int j = 0; j < count; j++) {
            float4 f = *(const float4*)(feat + (size_t)ssrc[j] * HC + t4);
            float w = swh[j];
            acc.x = fmaf(f.x, w, acc.x);
            acc.y = fmaf(f.y, w, acc.y);
            acc.z = fmaf(f.z, w, acc.z);
            acc.w = fmaf(f.w, w, acc.w);
        }
    }

    float4 b4 = *(const float4*)(bias + t4);
    float v0 = acc.x + b4.x, v1 = acc.y + b4.y, v2 = acc.z + b4.z, v3 = acc.w + b4.w;
    if (prelu) {
        float a = prelu_a[0];
        v0 = v0 >= 0.f ? v0 : a * v0;
        v1 = v1 >= 0.f ? v1 : a * v1;
        v2 = v2 >= 0.f ? v2 : a * v2;
        v3 = v3 >= 0.f ? v3 : a * v3;
    }
    size_t idx = (size_t)n * HC + t4;
    if (out) {
        *(float4*)(out + idx) = make_float4(v0, v1, v2, v3);
    }
    if (ohi) {
        __half h0 = __float2half_rn(v0);
        __half h1 = __float2half_rn(v1);
        __half h2 = __float2half_rn(v2);
        __half h3 = __float2half_rn(v3);
        __half2 hh01; hh01.x = h0; hh01.y = h1;
        __half2 hh23; hh23.x = h2; hh23.y = h3;
        *(__half2*)(ohi + idx)     = hh01;
        *(__half2*)(ohi + idx + 2) = hh23;
        __half2 ll01;
        ll01.x = __float2half_rn(v0 - __half2float(h0));
        ll01.y = __float2half_rn(v1 - __half2float(h1));
        __half2 ll23;
        ll23.x = __float2half_rn(v2 - __half2float(h2));
        ll23.y = __float2half_rn(v3 - __half2float(h3));
        *(__half2*)(olo + idx)     = ll01;
        *(__half2*)(olo + idx + 2) = ll23;
    }
}

// ---------------- host orchestration ----------------
static inline int ceil_div(int a, int b) { return (a + b - 1) / b; }

static void run_gemm(const __half* Ahi, const __half* Alo, const __half* Bf,
                     float* C, int M, int K, int N,
                     const float* asrc, const float* adst,
                     float* as_, float* ad_, int H, int Ch, int a_fp32) {
    dim3 grid(N / 128, ceil_div(M, 128));
    mma_gemm<<<grid, 256>>>(Ahi, Alo, Bf, C, M, K, N,
                            asrc, adst, as_, ad_, H, Ch, a_fp32);
}

extern "C" void kernel_launch(void* const* d_in, const int* in_sizes, int n_in,
                              void* d_out, int out_size) {
    const float* x       = (const float*)d_in[0];
    const void*  eidx    = d_in[1];
    const float* W1      = (const float*)d_in[2];
    const float* a_src1  = (const float*)d_in[3];
    const float* a_dst1  = (const float*)d_in[4];
    const float* b1      = (const float*)d_in[5];
    const float* prelu_a = (const float*)d_in[6];
    const float* W2      = (const float*)d_in[7];
    const float* a_src2  = (const float*)d_in[8];
    const float* a_dst2  = (const float*)d_in[9];
    const float* b2      = (const float*)d_in[10];
    const float* Wd      = (const float*)d_in[11];
    const float* a_srcd  = (const float*)d_in[12];
    const float* a_dstd  = (const float*)d_in[13];
    const float* bd      = (const float*)d_in[14];

    const int HHc = in_sizes[3];          // 512
    const int H1  = 4;
    const int C1  = HHc / H1;             // 128
    const int M   = in_sizes[8];          // 256
    const int D   = in_sizes[12];         // 256
    const int N   = in_sizes[0] / D;      // 50000
    const int E   = in_sizes[1] / 2;      // 400000
    const int ET  = E + N;

    float* out   = (float*)d_out;
    float* z     = out;
    float* x_hat = out + (size_t)N * M;

    float *h1, *h2, *hd;
    float *as1, *ad1, *as2, *ad2, *asd, *add;
    __half *ahi, *alo, *wt;
    int *cnt_p;
    cudaGetSymbolAddress((void**)&h1,  g_h1);
    cudaGetSymbolAddress((void**)&h2,  g_h2);
    cudaGetSymbolAddress((void**)&hd,  g_hd);
    cudaGetSymbolAddress((void**)&ahi, g_ahi);
    cudaGetSymbolAddress((void**)&alo, g_alo);
    cudaGetSymbolAddress((void**)&wt,  g_wt);
    cudaGetSymbolAddress((void**)&as1, g_as1);
    cudaGetSymbolAddress((void**)&ad1, g_ad1);
    cudaGetSymbolAddress((void**)&as2, g_as2);
    cudaGetSymbolAddress((void**)&ad2, g_ad2);
    cudaGetSymbolAddress((void**)&asd, g_asd);
    cudaGetSymbolAddress((void**)&add, g_add);
    cudaGetSymbolAddress((void**)&cnt_p, g_cnt);

    // ---- layer 1 GEMM (x split fused in-kernel); gemm1 stays 4th launch ----
    wtcvt_kernel<<<ceil_div(D * HHc, 256), 256>>>(W1, wt, D, HHc);
    zero_f2<<<ceil_div(N * H1, 256), 256>>>(as1, ad1, N * H1);
    zero_f2<<<ceil_div(N, 256), 256>>>(as2, ad2, N);
    run_gemm((const __half*)x, nullptr, wt, h1, N, D, HHc,
             a_src1, a_dst1, as1, ad1, H1, C1, 1);

    // ---- CSR build ----
    build_edges<<<ceil_div(ET, 256), 256>>>(eidx, E, N);
    zero_int<<<ceil_div(N, 256), 256>>>(cnt_p, N);
    hist_kernel<<<ceil_div(ET, 256), 256>>>(ET);
    int nb = ceil_div(N, 1024);
    scan1_kernel<<<nb, 1024>>>(N);
    scan2_kernel<<<1, 64>>>(nb);
    scan3_kernel<<<ceil_div(N, 256), 256>>>(N);
    copy_cursor<<<ceil_div(N, 256), 256>>>(N);
    scatter_kernel<<<ceil_div(ET, 256), 256>>>(ET);

    // ---- layer 1 aggregate (+PReLU, emits fp16 split for next GEMM) ----
    gat_aggregate<<<N, HHc / 4>>>(h1, as1, ad1, b1, nullptr, ahi, alo, H1, C1, 1, prelu_a);

    // ---- layer 2 ----
    wtcvt_kernel<<<ceil_div(HHc * M, 256), 256>>>(W2, wt, HHc, M);
    run_gemm(ahi, alo, wt, h2, N, HHc, M, a_src2, a_dst2, as2, ad2, 1, M, 0);
    zero_f2<<<ceil_div(N, 256), 256>>>(asd, add, N);
    gat_aggregate<<<N, M / 4>>>(h2, as2, ad2, b2, z, ahi, alo, 1, M, 0, prelu_a);

    // ---- decoder ----
    wtcvt_kernel<<<ceil_div(M * D, 256), 256>>>(Wd, wt, M, D);
    run_gemm(ahi, alo, wt, hd, N, M, D, a_srcd, a_dstd, asd, add, 1, D, 0);
    gat_aggregate<<<N, D / 4>>>(hd, asd, add, bd, x_hat, nullptr, nullptr, 1, D, 0, prelu_a);
}